// round 7
// baseline (speedup 1.0000x reference)
#include <cuda_runtime.h>
#include <cuda_fp16.h>

// ============================================================================
// SRU cell. L=2048, B=16, D=1024.
//   u = x @ W  -> fp16 mma.sync m16n8k16, fp16-acc promoted to fp32 per-mma.
//   Packed scratch g_U4[m][4d+{0,1,2,3}] = (u0,u1,u2, x*sqrt3) as fp16:
//   the scan inner loop is ONE 8-byte load per step.
// ============================================================================

#define L_DIM 2048
#define B_DIM 16
#define D_DIM 1024
#define N_DIM 3072
#define K_DIM 1024
#define M_DIM 32768  // L*B
#define P_DIM 4096   // packed row width (4*D)

#define BM 128
#define BN 128
#define BK 32
#define STAGES 4
#define ROWSTR_H 40
#define KT (K_DIM / BK)
#define STAGE_H (2 * BM * ROWSTR_H)
#define GEMM_SMEM_BYTES (STAGES * STAGE_H * 2) // 81920

// Scratch (allocation-free rule: __device__ globals)
__device__ __half g_Xh[(size_t)M_DIM * K_DIM];   // X fp16 (64 MB)
__device__ __half g_Wh[N_DIM * K_DIM];           // W^T fp16 (6 MB)
__device__ __half g_U4[(size_t)M_DIM * P_DIM];   // packed (u0,u1,u2,x*SC) (268 MB)

// ---------------------------------------------------------------------------
__device__ __forceinline__ unsigned smem_u32(const void* p) {
    unsigned a;
    asm("{ .reg .u64 t; cvta.to.shared.u64 t, %1; cvt.u32.u64 %0, t; }" : "=r"(a) : "l"(p));
    return a;
}

__device__ __forceinline__ void cp_async16(unsigned dst, const void* src) {
    asm volatile("cp.async.cg.shared.global [%0], [%1], 16;" :: "r"(dst), "l"(src));
}

__device__ __forceinline__ void ldmatrix_x4(unsigned& r0, unsigned& r1,
                                            unsigned& r2, unsigned& r3, unsigned addr) {
    asm volatile("ldmatrix.sync.aligned.m8n8.x4.shared.b16 {%0,%1,%2,%3}, [%4];"
                 : "=r"(r0), "=r"(r1), "=r"(r2), "=r"(r3) : "r"(addr));
}

__device__ __forceinline__ void mma_f16acc(unsigned& c0, unsigned& c1,
                                           const unsigned* a, const unsigned* b) {
    c0 = 0u; c1 = 0u;
    asm volatile(
        "mma.sync.aligned.m16n8k16.row.col.f16.f16.f16.f16 "
        "{%0,%1}, {%2,%3,%4,%5}, {%6,%7}, {%0,%1};"
        : "+r"(c0), "+r"(c1)
        : "r"(a[0]), "r"(a[1]), "r"(a[2]), "r"(a[3]), "r"(b[0]), "r"(b[1]));
}

#define SC_F 1.7320508075688772f  // sqrt(1 + 2*e^0)

// ---------------------------------------------------------------------------
// Kernel 0: X -> fp16 (for GEMM A) and x*SC -> packed slot 3
// Each thread: 8 consecutive d of one (l,b) row.
// ---------------------------------------------------------------------------
__global__ void __launch_bounds__(256) convert_x(const float* __restrict__ X) {
    size_t i8 = (size_t)blockIdx.x * 256 + threadIdx.x;
    size_t i = i8 * 8;
    int m = (int)(i >> 10);          // row (l*16+b)
    int d0 = (int)(i & 1023);
    float4 a = *(const float4*)(X + i);
    float4 b = *(const float4*)(X + i + 4);
    __half2 h0 = __floats2half2_rn(a.x, a.y);
    __half2 h1 = __floats2half2_rn(a.z, a.w);
    __half2 h2 = __floats2half2_rn(b.x, b.y);
    __half2 h3 = __floats2half2_rn(b.z, b.w);
    uint4 o;
    o.x = *(unsigned*)&h0; o.y = *(unsigned*)&h1;
    o.z = *(unsigned*)&h2; o.w = *(unsigned*)&h3;
    *(uint4*)(g_Xh + i) = o;

    __half* up = g_U4 + (size_t)m * P_DIM + 4 * d0 + 3;
    float v[8] = {a.x, a.y, a.z, a.w, b.x, b.y, b.z, b.w};
#pragma unroll
    for (int j = 0; j < 8; j++)
        up[4 * j] = __float2half_rn(v[j] * SC_F);
}

// ---------------------------------------------------------------------------
// Kernel 1: transpose W (K,N) -> W^T (N,K) fp16
// ---------------------------------------------------------------------------
__global__ void transpose_w(const float* __restrict__ W) {
    __shared__ float t[32][33];
    int n0 = blockIdx.x * 32, k0 = blockIdx.y * 32;
    int tx = threadIdx.x, ty = threadIdx.y;  // 32 x 8
#pragma unroll
    for (int i = 0; i < 32; i += 8)
        t[ty + i][tx] = W[(size_t)(k0 + ty + i) * N_DIM + n0 + tx];
    __syncthreads();
#pragma unroll
    for (int i = 0; i < 32; i += 8)
        g_Wh[(size_t)(n0 + ty + i) * K_DIM + k0 + tx] = __float2half_rn(t[tx][ty + i]);
}

// ---------------------------------------------------------------------------
// Kernel 2: fp16 GEMM (unchanged mainloop), epilogue writes packed slots.
// ---------------------------------------------------------------------------
__device__ __forceinline__ void write_u_pair(int row, int col, float a, float b) {
    int d = col / 3, cm = col - 3 * d;
    size_t base = (size_t)row * P_DIM + 4 * d + cm;
    if (cm == 0) {
        __half2 h = __floats2half2_rn(a, b);
        *(unsigned*)&g_U4[base] = *(unsigned*)&h;   // slots 4d,4d+1 (4B aligned)
    } else if (cm == 1) {
        g_U4[base]     = __float2half_rn(a);        // 4d+1
        g_U4[base + 1] = __float2half_rn(b);        // 4d+2
    } else {
        g_U4[base]     = __float2half_rn(a);        // 4d+2
        g_U4[base + 2] = __float2half_rn(b);        // 4(d+1)
    }
}

__global__ void __launch_bounds__(256, 2) gemm_f16() {
    extern __shared__ __half smem_h[];
    unsigned sbase = smem_u32(smem_h);

    int tid = threadIdx.x;
    int wid = tid >> 5;
    int lid = tid & 31;
    int g   = lid >> 2;
    int t4  = lid & 3;
    int q   = lid >> 3;
    int rr  = lid & 7;
    int warp_m = wid >> 1;
    int warp_n = wid & 1;
    int mbase = warp_m * 32;
    int nbase = warp_n * 64;

    int n0 = blockIdx.x * BN;
    int m0 = blockIdx.y * BM;

    const __half* Arow = g_Xh + (size_t)m0 * K_DIM;
    const __half* Brow = g_Wh + (size_t)n0 * K_DIM;
    const int B_OFF_H = BM * ROWSTR_H;

    float acc[2][8][4];
#pragma unroll
    for (int mt = 0; mt < 2; mt++)
#pragma unroll
        for (int nt = 0; nt < 8; nt++)
#pragma unroll
            for (int i = 0; i < 4; i++) acc[mt][nt][i] = 0.0f;

    auto load_stage = [&](int stage, int kc) {
        unsigned sA = sbase + (unsigned)(stage * STAGE_H) * 2u;
        unsigned sB = sA + (unsigned)B_OFF_H * 2u;
#pragma unroll
        for (int t = 0; t < 2; t++) {
            int j = tid + t * 256;
            int row = j >> 2;
            int c = j & 3;
            unsigned off = (unsigned)(row * ROWSTR_H + c * 8) * 2u;
            cp_async16(sA + off, Arow + (size_t)row * K_DIM + kc + c * 8);
            cp_async16(sB + off, Brow + (size_t)row * K_DIM + kc + c * 8);
        }
        asm volatile("cp.async.commit_group;" ::: "memory");
    };

#pragma unroll
    for (int s = 0; s < STAGES - 1; s++) load_stage(s, s * BK);

    for (int kt = 0; kt < KT; kt++) {
        asm volatile("cp.async.wait_group %0;" :: "n"(STAGES - 2) : "memory");
        __syncthreads();

        if (kt + STAGES - 1 < KT)
            load_stage((kt + STAGES - 1) % STAGES, (kt + STAGES - 1) * BK);
        else
            asm volatile("cp.async.commit_group;" ::: "memory");

        unsigned stA = sbase + (unsigned)((kt % STAGES) * STAGE_H) * 2u;
        unsigned stB = stA + (unsigned)B_OFF_H * 2u;

#pragma unroll
        for (int kk = 0; kk < 2; kk++) {
            unsigned a[2][4];
#pragma unroll
            for (int mt = 0; mt < 2; mt++) {
                int row = mbase + mt * 16 + ((q & 1) << 3) + rr;
                int kh  = kk * 16 + (q >> 1) * 8;
                ldmatrix_x4(a[mt][0], a[mt][1], a[mt][2], a[mt][3],
                            stA + (unsigned)(row * ROWSTR_H + kh) * 2u);
            }
            unsigned b[8][2];
#pragma unroll
            for (int nt2 = 0; nt2 < 4; nt2++) {
                int row = nbase + nt2 * 16 + ((q >> 1) << 3) + rr;
                int kh  = kk * 16 + (q & 1) * 8;
                ldmatrix_x4(b[nt2 * 2][0], b[nt2 * 2][1], b[nt2 * 2 + 1][0], b[nt2 * 2 + 1][1],
                            stB + (unsigned)(row * ROWSTR_H + kh) * 2u);
            }
#pragma unroll
            for (int mt = 0; mt < 2; mt++)
#pragma unroll
                for (int nt = 0; nt < 8; nt++) {
                    unsigned c0, c1;
                    mma_f16acc(c0, c1, a[mt], b[nt]);
                    float2 f0 = __half22float2(*(__half2*)&c0);
                    float2 f1 = __half22float2(*(__half2*)&c1);
                    acc[mt][nt][0] += f0.x;
                    acc[mt][nt][1] += f0.y;
                    acc[mt][nt][2] += f1.x;
                    acc[mt][nt][3] += f1.y;
                }
        }
    }

    // ---- epilogue: packed-slot stores ----
#pragma unroll
    for (int mt = 0; mt < 2; mt++) {
#pragma unroll
        for (int nt = 0; nt < 8; nt++) {
            int row = m0 + mbase + mt * 16 + g;
            int col = n0 + nbase + nt * 8 + 2 * t4;
            write_u_pair(row,     col, acc[mt][nt][0], acc[mt][nt][1]);
            write_u_pair(row + 8, col, acc[mt][nt][2], acc[mt][nt][3]);
        }
    }
}

// ---------------------------------------------------------------------------
// Kernel 3: SRU scan. One LDG.64 per step; 16-deep double-buffered prefetch.
// ---------------------------------------------------------------------------
#define PF 16

__global__ void __launch_bounds__(64) sru_scan(const float* __restrict__ C0,
                                               const float* __restrict__ Wc,
                                               const float* __restrict__ Bias,
                                               float* __restrict__ Out,
                                               int write_c) {
    int ch = blockIdx.x * 64 + threadIdx.x;  // 0..16383
    int d = ch & (D_DIM - 1);
    int b = ch >> 10;

    float fw = Wc[d], rw = Wc[D_DIM + d];
    float fb = Bias[d], rb = Bias[D_DIM + d];
    float c = C0[ch];

    const __half* up = g_U4 + (size_t)b * P_DIM + 4 * d;
    float* hp = Out + ch;

    const size_t US = (size_t)B_DIM * P_DIM;   // halves per step
    const size_t XS = (size_t)B_DIM * D_DIM;   // floats per step

    uint2 buf[2][PF];
#pragma unroll
    for (int j = 0; j < PF; j++)
        buf[0][j] = *(const uint2*)(up + (size_t)j * US);

#pragma unroll 2
    for (int l = 0; l < L_DIM; l += PF) {
        int p = (l / PF) & 1;
        if (l + PF < L_DIM) {
#pragma unroll
            for (int j = 0; j < PF; j++)
                buf[p ^ 1][j] = *(const uint2*)(up + (size_t)(PF + j) * US);
        }
#pragma unroll
        for (int j = 0; j < PF; j++) {
            uint2 v = buf[p][j];
            float2 p01 = __half22float2(*(__half2*)&v.x);   // (u0, u1)
            float2 p23 = __half22float2(*(__half2*)&v.y);   // (u2, x*SC)
            float u0 = p01.x, u1 = p01.y, u2 = p23.x, xv = p23.y;
            float z1 = fmaf(c, fw, u1 + fb);
            float z2 = fmaf(c, rw, u2 + rb);
            float f = 1.0f / (1.0f + __expf(-z1));
            float r = 1.0f / (1.0f + __expf(-z2));
            c = u0 + (c - u0) * f;
            hp[(size_t)j * XS] = xv + (c - xv) * r;
        }
        up += (size_t)PF * US;
        hp += (size_t)PF * XS;
    }
    if (write_c) Out[(size_t)L_DIM * B_DIM * D_DIM + ch] = c;
}

// ---------------------------------------------------------------------------
extern "C" void kernel_launch(void* const* d_in, const int* in_sizes, int n_in,
                              void* d_out, int out_size) {
    const float* x    = (const float*)d_in[0];
    const float* c0   = (const float*)d_in[1];
    const float* w    = (const float*)d_in[2];
    const float* wc   = (const float*)d_in[3];
    const float* bias = (const float*)d_in[4];
    float* out = (float*)d_out;

    int write_c = (out_size >= L_DIM * B_DIM * D_DIM + B_DIM * D_DIM) ? 1 : 0;

    static int smem_set = 0;
    if (!smem_set) {
        cudaFuncSetAttribute(gemm_f16, cudaFuncAttributeMaxDynamicSharedMemorySize,
                             GEMM_SMEM_BYTES);
        smem_set = 1;
    }

    convert_x<<<(M_DIM * (K_DIM / 8)) / 256, 256>>>(x);
    transpose_w<<<dim3(N_DIM / 32, K_DIM / 32), dim3(32, 8)>>>(w);
    gemm_f16<<<dim3(N_DIM / BN, M_DIM / BM), 256, GEMM_SMEM_BYTES>>>();
    sru_scan<<<(B_DIM * D_DIM) / 64, 64>>>(c0, wc, bias, out, write_c);
}

// round 8
// speedup vs baseline: 1.0204x; 1.0204x over previous
#include <cuda_runtime.h>
#include <cuda_fp16.h>

// ============================================================================
// SRU cell. L=2048, B=16, D=1024.
//   u = x @ W  -> fp16 mma.sync m16n8k16, fp16-acc promoted to fp32 per-mma.
//   BN=96 tiles: 96 cols = 32 whole channels -> epilogue writes COMPLETE
//   packed records (u0,u1,u2,x*sqrt3) as coalesced uint2.
//   Scan: one LDG.64/step, 2 interleaved chains/thread, ex2/rcp approx.
// ============================================================================

#define L_DIM 2048
#define B_DIM 16
#define D_DIM 1024
#define N_DIM 3072
#define K_DIM 1024
#define M_DIM 32768  // L*B
#define P_DIM 4096   // packed row width (4*D) halves

#define BM 128
#define BN 96
#define BK 32
#define STAGES 4
#define ROWSTR_H 40
#define KT (K_DIM / BK)
#define B_OFF_H (BM * ROWSTR_H)                 // 5120
#define STAGE_H ((BM + BN) * ROWSTR_H)          // 8960 halves
#define GEMM_SMEM_BYTES (STAGES * STAGE_H * 2)  // 71680

#define SC_F   1.7320508075688772f  // sqrt(1 + 2*e^0)
#define LOG2E  1.4426950408889634f

// Scratch (allocation-free rule: __device__ globals)
__device__ __half g_Xh[(size_t)M_DIM * K_DIM];   // X fp16 (64 MB)
__device__ __half g_Wh[N_DIM * K_DIM];           // W^T fp16 (6 MB)
__device__ __half g_U4[(size_t)M_DIM * P_DIM];   // packed (u0,u1,u2,x*SC) (268 MB)

// ---------------------------------------------------------------------------
__device__ __forceinline__ unsigned smem_u32(const void* p) {
    unsigned a;
    asm("{ .reg .u64 t; cvta.to.shared.u64 t, %1; cvt.u32.u64 %0, t; }" : "=r"(a) : "l"(p));
    return a;
}

__device__ __forceinline__ void cp_async16(unsigned dst, const void* src) {
    asm volatile("cp.async.cg.shared.global [%0], [%1], 16;" :: "r"(dst), "l"(src));
}

__device__ __forceinline__ void ldmatrix_x4(unsigned& r0, unsigned& r1,
                                            unsigned& r2, unsigned& r3, unsigned addr) {
    asm volatile("ldmatrix.sync.aligned.m8n8.x4.shared.b16 {%0,%1,%2,%3}, [%4];"
                 : "=r"(r0), "=r"(r1), "=r"(r2), "=r"(r3) : "r"(addr));
}

__device__ __forceinline__ void mma_f16acc(unsigned& c0, unsigned& c1,
                                           const unsigned* a, const unsigned* b) {
    c0 = 0u; c1 = 0u;
    asm volatile(
        "mma.sync.aligned.m16n8k16.row.col.f16.f16.f16.f16 "
        "{%0,%1}, {%2,%3,%4,%5}, {%6,%7}, {%0,%1};"
        : "+r"(c0), "+r"(c1)
        : "r"(a[0]), "r"(a[1]), "r"(a[2]), "r"(a[3]), "r"(b[0]), "r"(b[1]));
}

__device__ __forceinline__ float ex2f(float x) {
    float r; asm("ex2.approx.f32 %0, %1;" : "=f"(r) : "f"(x)); return r;
}
__device__ __forceinline__ float rcpf(float x) {
    float r; asm("rcp.approx.f32 %0, %1;" : "=f"(r) : "f"(x)); return r;
}

// ---------------------------------------------------------------------------
// Kernel 0: X -> fp16
// ---------------------------------------------------------------------------
__global__ void __launch_bounds__(256) convert_x(const float* __restrict__ X) {
    size_t i = ((size_t)blockIdx.x * 256 + threadIdx.x) * 8;
    float4 a = *(const float4*)(X + i);
    float4 b = *(const float4*)(X + i + 4);
    __half2 h0 = __floats2half2_rn(a.x, a.y);
    __half2 h1 = __floats2half2_rn(a.z, a.w);
    __half2 h2 = __floats2half2_rn(b.x, b.y);
    __half2 h3 = __floats2half2_rn(b.z, b.w);
    uint4 o;
    o.x = *(unsigned*)&h0; o.y = *(unsigned*)&h1;
    o.z = *(unsigned*)&h2; o.w = *(unsigned*)&h3;
    *(uint4*)(g_Xh + i) = o;
}

// ---------------------------------------------------------------------------
// Kernel 1: transpose W (K,N) -> W^T (N,K) fp16
// ---------------------------------------------------------------------------
__global__ void transpose_w(const float* __restrict__ W) {
    __shared__ float t[32][33];
    int n0 = blockIdx.x * 32, k0 = blockIdx.y * 32;
    int tx = threadIdx.x, ty = threadIdx.y;  // 32 x 8
#pragma unroll
    for (int i = 0; i < 32; i += 8)
        t[ty + i][tx] = W[(size_t)(k0 + ty + i) * N_DIM + n0 + tx];
    __syncthreads();
#pragma unroll
    for (int i = 0; i < 32; i += 8)
        g_Wh[(size_t)(n0 + ty + i) * K_DIM + k0 + tx] = __float2half_rn(t[tx][ty + i]);
}

// ---------------------------------------------------------------------------
// Kernel 2: fp16 GEMM, CTA 128x96. Epilogue: smem stage -> coalesced uint2
// packed records (slot 3 = x*SC from g_Xh).
// 8 warps: 4(M) x 2(N); warp tile 32 x 48.
// ---------------------------------------------------------------------------
#define EP_STR 104   // halves per staged row (96 + 8 pad)

__global__ void __launch_bounds__(256, 2) gemm_f16() {
    extern __shared__ __half smem_h[];
    unsigned sbase = smem_u32(smem_h);

    int tid = threadIdx.x;
    int wid = tid >> 5;
    int lid = tid & 31;
    int g   = lid >> 2;
    int t4  = lid & 3;
    int q   = lid >> 3;
    int rr  = lid & 7;
    int warp_m = wid >> 1;   // 0..3
    int warp_n = wid & 1;    // 0..1
    int mbase = warp_m * 32;
    int nbase = warp_n * 48;

    int n0 = blockIdx.x * BN;        // multiple of 96
    int d0 = n0 / 3;                 // 32 channels per CTA
    int m0 = blockIdx.y * BM;

    const __half* Arow = g_Xh + (size_t)m0 * K_DIM;
    const __half* Brow = g_Wh + (size_t)n0 * K_DIM;

    float acc[2][6][4];
#pragma unroll
    for (int mt = 0; mt < 2; mt++)
#pragma unroll
        for (int nt = 0; nt < 6; nt++)
#pragma unroll
            for (int i = 0; i < 4; i++) acc[mt][nt][i] = 0.0f;

    // stage: A 128 rows + B 96 rows, 4 x 16B chunks per row = 896 chunks.
    auto load_stage = [&](int stage, int kc) {
        unsigned s0 = sbase + (unsigned)(stage * STAGE_H) * 2u;
        for (int j = tid; j < 896; j += 256) {
            int isB = j >= 512;
            int jj  = isB ? j - 512 : j;
            int row = jj >> 2;
            int c   = jj & 3;
            unsigned off = (unsigned)((isB ? B_OFF_H : 0) + row * ROWSTR_H + c * 8) * 2u;
            const __half* src = (isB ? Brow : Arow) + (size_t)row * K_DIM + kc + c * 8;
            cp_async16(s0 + off, src);
        }
        asm volatile("cp.async.commit_group;" ::: "memory");
    };

#pragma unroll
    for (int s = 0; s < STAGES - 1; s++) load_stage(s, s * BK);

    for (int kt = 0; kt < KT; kt++) {
        asm volatile("cp.async.wait_group %0;" :: "n"(STAGES - 2) : "memory");
        __syncthreads();

        if (kt + STAGES - 1 < KT)
            load_stage((kt + STAGES - 1) % STAGES, (kt + STAGES - 1) * BK);
        else
            asm volatile("cp.async.commit_group;" ::: "memory");

        unsigned stA = sbase + (unsigned)((kt % STAGES) * STAGE_H) * 2u;
        unsigned stB = stA + (unsigned)B_OFF_H * 2u;

#pragma unroll
        for (int kk = 0; kk < 2; kk++) {
            unsigned a[2][4];
#pragma unroll
            for (int mt = 0; mt < 2; mt++) {
                int row = mbase + mt * 16 + ((q & 1) << 3) + rr;
                int kh  = kk * 16 + (q >> 1) * 8;
                ldmatrix_x4(a[mt][0], a[mt][1], a[mt][2], a[mt][3],
                            stA + (unsigned)(row * ROWSTR_H + kh) * 2u);
            }
            unsigned b[6][2];
#pragma unroll
            for (int nt2 = 0; nt2 < 3; nt2++) {
                int row = nbase + nt2 * 16 + ((q >> 1) << 3) + rr;
                int kh  = kk * 16 + (q & 1) * 8;
                ldmatrix_x4(b[nt2 * 2][0], b[nt2 * 2][1], b[nt2 * 2 + 1][0], b[nt2 * 2 + 1][1],
                            stB + (unsigned)(row * ROWSTR_H + kh) * 2u);
            }
#pragma unroll
            for (int mt = 0; mt < 2; mt++)
#pragma unroll
                for (int nt = 0; nt < 6; nt++) {
                    unsigned c0, c1;
                    mma_f16acc(c0, c1, a[mt], b[nt]);
                    float2 f0 = __half22float2(*(__half2*)&c0);
                    float2 f1 = __half22float2(*(__half2*)&c1);
                    acc[mt][nt][0] += f0.x;
                    acc[mt][nt][1] += f0.y;
                    acc[mt][nt][2] += f1.x;
                    acc[mt][nt][3] += f1.y;
                }
        }
    }

    // ---- epilogue: stage fp16 tile in smem, then coalesced packed records ----
    __syncthreads();
    __half* st = smem_h;   // 128 x EP_STR halves = 26624 halves (fits in 71KB)
#pragma unroll
    for (int mt = 0; mt < 2; mt++) {
#pragma unroll
        for (int nt = 0; nt < 6; nt++) {
            int row = mbase + mt * 16 + g;
            int col = nbase + nt * 8 + 2 * t4;
            __half2 h0 = __floats2half2_rn(acc[mt][nt][0], acc[mt][nt][1]);
            __half2 h1 = __floats2half2_rn(acc[mt][nt][2], acc[mt][nt][3]);
            *(__half2*)&st[row * EP_STR + col] = h0;
            *(__half2*)&st[(row + 8) * EP_STR + col] = h1;
        }
    }
    __syncthreads();

    // 128 rows x 32 channels = 4096 records; warp = one row (256B contiguous)
    for (int j = tid; j < 4096; j += 256) {
        int row = j >> 5;
        int dl  = j & 31;
        int m   = m0 + row;
        __half u0 = st[row * EP_STR + 3 * dl];
        __half u1 = st[row * EP_STR + 3 * dl + 1];
        __half u2 = st[row * EP_STR + 3 * dl + 2];
        float xs = __half2float(g_Xh[(size_t)m * K_DIM + d0 + dl]) * SC_F;
        __half2 lo, hi;
        lo = __halves2half2(u0, u1);
        hi = __halves2half2(u2, __float2half_rn(xs));
        uint2 v;
        v.x = *(unsigned*)&lo;
        v.y = *(unsigned*)&hi;
        *(uint2*)&g_U4[(size_t)m * P_DIM + 4 * (d0 + dl)] = v;
    }
}

// ---------------------------------------------------------------------------
// Kernel 3: SRU scan. 8192 threads, 2 interleaved chains each (b, b+8).
// One LDG.64 per chain-step; PF=8 double-buffered; ex2/rcp approx.
// ---------------------------------------------------------------------------
#define PF 8

__global__ void __launch_bounds__(64) sru_scan(const float* __restrict__ C0,
                                               const float* __restrict__ Wc,
                                               const float* __restrict__ Bias,
                                               float* __restrict__ Out,
                                               int write_c) {
    int t = blockIdx.x * 64 + threadIdx.x;   // 0..8191
    int d  = t & (D_DIM - 1);
    int b0 = t >> 10;                        // 0..7

    float fw = Wc[d], rw = Wc[D_DIM + d];
    float fb = Bias[d], rb = Bias[D_DIM + d];
    // fold -log2e into the ex2 argument; bias terms off the critical path
    float fwl = -fw * LOG2E, rwl = -rw * LOG2E;
    float fbl = -fb * LOG2E, rbl = -rb * LOG2E;

    int chA = b0 * D_DIM + d;
    int chB = chA + 8 * D_DIM;
    float cA = C0[chA], cB = C0[chB];

    const __half* upA = g_U4 + (size_t)b0 * P_DIM + 4 * d;
    const __half* upB = upA + (size_t)8 * P_DIM;
    float* hpA = Out + chA;
    float* hpB = Out + chB;

    const size_t US = (size_t)B_DIM * P_DIM;   // halves per step
    const size_t XS = (size_t)B_DIM * D_DIM;   // floats per step

    uint2 bufA[2][PF], bufB[2][PF];
#pragma unroll
    for (int j = 0; j < PF; j++) {
        bufA[0][j] = *(const uint2*)(upA + (size_t)j * US);
        bufB[0][j] = *(const uint2*)(upB + (size_t)j * US);
    }

#pragma unroll 2
    for (int l = 0; l < L_DIM; l += PF) {
        int p = (l / PF) & 1;
        if (l + PF < L_DIM) {
#pragma unroll
            for (int j = 0; j < PF; j++) {
                bufA[p ^ 1][j] = *(const uint2*)(upA + (size_t)(PF + j) * US);
                bufB[p ^ 1][j] = *(const uint2*)(upB + (size_t)(PF + j) * US);
            }
        }
#pragma unroll
        for (int j = 0; j < PF; j++) {
            // chain A
            {
                uint2 v = bufA[p][j];
                float2 p01 = __half22float2(*(__half2*)&v.x);
                float2 p23 = __half22float2(*(__half2*)&v.y);
                float u0 = p01.x, u1 = p01.y, u2 = p23.x, xv = p23.y;
                float a1 = fmaf(u1, -LOG2E, fbl);      // -(u1+fb)*log2e
                float a2 = fmaf(u2, -LOG2E, rbl);
                float f = rcpf(1.0f + ex2f(fmaf(cA, fwl, a1)));
                float r = rcpf(1.0f + ex2f(fmaf(cA, rwl, a2)));
                cA = u0 + (cA - u0) * f;
                hpA[(size_t)j * XS] = xv + (cA - xv) * r;
            }
            // chain B (independent; fills chain A's stalls)
            {
                uint2 v = bufB[p][j];
                float2 p01 = __half22float2(*(__half2*)&v.x);
                float2 p23 = __half22float2(*(__half2*)&v.y);
                float u0 = p01.x, u1 = p01.y, u2 = p23.x, xv = p23.y;
                float a1 = fmaf(u1, -LOG2E, fbl);
                float a2 = fmaf(u2, -LOG2E, rbl);
                float f = rcpf(1.0f + ex2f(fmaf(cB, fwl, a1)));
                float r = rcpf(1.0f + ex2f(fmaf(cB, rwl, a2)));
                cB = u0 + (cB - u0) * f;
                hpB[(size_t)j * XS] = xv + (cB - xv) * r;
            }
        }
        upA += (size_t)PF * US;
        upB += (size_t)PF * US;
        hpA += (size_t)PF * XS;
        hpB += (size_t)PF * XS;
    }
    if (write_c) {
        Out[(size_t)L_DIM * B_DIM * D_DIM + chA] = cA;
        Out[(size_t)L_DIM * B_DIM * D_DIM + chB] = cB;
    }
}

// ---------------------------------------------------------------------------
extern "C" void kernel_launch(void* const* d_in, const int* in_sizes, int n_in,
                              void* d_out, int out_size) {
    const float* x    = (const float*)d_in[0];
    const float* c0   = (const float*)d_in[1];
    const float* w    = (const float*)d_in[2];
    const float* wc   = (const float*)d_in[3];
    const float* bias = (const float*)d_in[4];
    float* out = (float*)d_out;

    int write_c = (out_size >= L_DIM * B_DIM * D_DIM + B_DIM * D_DIM) ? 1 : 0;

    static int smem_set = 0;
    if (!smem_set) {
        cudaFuncSetAttribute(gemm_f16, cudaFuncAttributeMaxDynamicSharedMemorySize,
                             GEMM_SMEM_BYTES);
        smem_set = 1;
    }

    convert_x<<<(M_DIM * (K_DIM / 8)) / 256, 256>>>(x);
    transpose_w<<<dim3(N_DIM / 32, K_DIM / 32), dim3(32, 8)>>>(w);
    gemm_f16<<<dim3(N_DIM / BN, M_DIM / BM), 256, GEMM_SMEM_BYTES>>>();
    sru_scan<<<(B_DIM * D_DIM / 2) / 64, 64>>>(c0, wc, bias, out, write_c);
}

// round 9
// speedup vs baseline: 1.4657x; 1.4365x over previous
#include <cuda_runtime.h>
#include <cuda_fp16.h>

// ============================================================================
// SRU cell. L=2048, B=16, D=1024.  (R6 structure + approx-math scan)
//   u = x @ W  -> fp16 mma.sync m16n8k16, fp16-acc promoted to fp32 per-mma.
//   U stored as fp16 in natural [m][n] layout (coalesced epilogue).
//   scan: 16-deep double-buffered prefetch, ex2/rcp approx sigmoid
//   (removes div.rn from the serial c-chain).
// ============================================================================

#define L_DIM 2048
#define B_DIM 16
#define D_DIM 1024
#define N_DIM 3072
#define K_DIM 1024
#define M_DIM 32768  // L*B

#define BM 128
#define BN 128
#define BK 32
#define STAGES 4
#define ROWSTR_H 40                // halves per smem row (64B data + 16B pad)
#define KT (K_DIM / BK)            // 32
#define STAGE_H (2 * BM * ROWSTR_H)            // 10240 halves
#define GEMM_SMEM_BYTES (STAGES * STAGE_H * 2) // 81920

#define LOG2E 1.4426950408889634f

// Scratch (allocation-free rule: __device__ globals)
__device__ __half g_Xh[(size_t)M_DIM * K_DIM];  // X fp16 (64 MB)
__device__ __half g_Wh[N_DIM * K_DIM];          // W^T fp16 (6 MB)
__device__ __half g_Uh[(size_t)M_DIM * N_DIM];  // GEMM output u, fp16 (201 MB)

// ---------------------------------------------------------------------------
__device__ __forceinline__ unsigned smem_u32(const void* p) {
    unsigned a;
    asm("{ .reg .u64 t; cvta.to.shared.u64 t, %1; cvt.u32.u64 %0, t; }" : "=r"(a) : "l"(p));
    return a;
}

__device__ __forceinline__ void cp_async16(unsigned dst, const void* src) {
    asm volatile("cp.async.cg.shared.global [%0], [%1], 16;" :: "r"(dst), "l"(src));
}

__device__ __forceinline__ void ldmatrix_x4(unsigned& r0, unsigned& r1,
                                            unsigned& r2, unsigned& r3, unsigned addr) {
    asm volatile("ldmatrix.sync.aligned.m8n8.x4.shared.b16 {%0,%1,%2,%3}, [%4];"
                 : "=r"(r0), "=r"(r1), "=r"(r2), "=r"(r3) : "r"(addr));
}

__device__ __forceinline__ void mma_f16acc(unsigned& c0, unsigned& c1,
                                           const unsigned* a, const unsigned* b) {
    c0 = 0u; c1 = 0u;
    asm volatile(
        "mma.sync.aligned.m16n8k16.row.col.f16.f16.f16.f16 "
        "{%0,%1}, {%2,%3,%4,%5}, {%6,%7}, {%0,%1};"
        : "+r"(c0), "+r"(c1)
        : "r"(a[0]), "r"(a[1]), "r"(a[2]), "r"(a[3]), "r"(b[0]), "r"(b[1]));
}

__device__ __forceinline__ float ex2f(float x) {
    float r; asm("ex2.approx.f32 %0, %1;" : "=f"(r) : "f"(x)); return r;
}
__device__ __forceinline__ float rcpf(float x) {
    float r; asm("rcp.approx.f32 %0, %1;" : "=f"(r) : "f"(x)); return r;
}

// ---------------------------------------------------------------------------
// Kernel 0: convert X -> fp16
// ---------------------------------------------------------------------------
__global__ void __launch_bounds__(256) convert_x(const float* __restrict__ X) {
    size_t i = ((size_t)blockIdx.x * 256 + threadIdx.x) * 8;
    float4 a = *(const float4*)(X + i);
    float4 b = *(const float4*)(X + i + 4);
    __half2 h0 = __floats2half2_rn(a.x, a.y);
    __half2 h1 = __floats2half2_rn(a.z, a.w);
    __half2 h2 = __floats2half2_rn(b.x, b.y);
    __half2 h3 = __floats2half2_rn(b.z, b.w);
    uint4 o;
    o.x = *(unsigned*)&h0; o.y = *(unsigned*)&h1;
    o.z = *(unsigned*)&h2; o.w = *(unsigned*)&h3;
    *(uint4*)(g_Xh + i) = o;
}

// ---------------------------------------------------------------------------
// Kernel 1: transpose W (K,N) -> W^T (N,K) fp16
// ---------------------------------------------------------------------------
__global__ void transpose_w(const float* __restrict__ W) {
    __shared__ float t[32][33];
    int n0 = blockIdx.x * 32, k0 = blockIdx.y * 32;
    int tx = threadIdx.x, ty = threadIdx.y;  // 32 x 8
#pragma unroll
    for (int i = 0; i < 32; i += 8)
        t[ty + i][tx] = W[(size_t)(k0 + ty + i) * N_DIM + n0 + tx];
    __syncthreads();
#pragma unroll
    for (int i = 0; i < 32; i += 8)
        g_Wh[(size_t)(n0 + ty + i) * K_DIM + k0 + tx] = __float2half_rn(t[tx][ty + i]);
}

// ---------------------------------------------------------------------------
// Kernel 2: fp16 GEMM, fp16-acc mma + per-mma fp32 promotion.
// CTA 128x128, BK=32, 4-stage cp.async, 8 warps 4(M)x2(N), warp 32x64.
// ---------------------------------------------------------------------------
__global__ void __launch_bounds__(256, 2) gemm_f16() {
    extern __shared__ __half smem_h[];
    unsigned sbase = smem_u32(smem_h);

    int tid = threadIdx.x;
    int wid = tid >> 5;
    int lid = tid & 31;
    int g   = lid >> 2;
    int t4  = lid & 3;
    int q   = lid >> 3;
    int rr  = lid & 7;
    int warp_m = wid >> 1;
    int warp_n = wid & 1;
    int mbase = warp_m * 32;
    int nbase = warp_n * 64;

    int n0 = blockIdx.x * BN;
    int m0 = blockIdx.y * BM;

    const __half* Arow = g_Xh + (size_t)m0 * K_DIM;
    const __half* Brow = g_Wh + (size_t)n0 * K_DIM;
    const int B_OFF_H = BM * ROWSTR_H;

    float acc[2][8][4];
#pragma unroll
    for (int mt = 0; mt < 2; mt++)
#pragma unroll
        for (int nt = 0; nt < 8; nt++)
#pragma unroll
            for (int i = 0; i < 4; i++) acc[mt][nt][i] = 0.0f;

    auto load_stage = [&](int stage, int kc) {
        unsigned sA = sbase + (unsigned)(stage * STAGE_H) * 2u;
        unsigned sB = sA + (unsigned)B_OFF_H * 2u;
#pragma unroll
        for (int t = 0; t < 2; t++) {
            int j = tid + t * 256;
            int row = j >> 2;
            int c = j & 3;
            unsigned off = (unsigned)(row * ROWSTR_H + c * 8) * 2u;
            cp_async16(sA + off, Arow + (size_t)row * K_DIM + kc + c * 8);
            cp_async16(sB + off, Brow + (size_t)row * K_DIM + kc + c * 8);
        }
        asm volatile("cp.async.commit_group;" ::: "memory");
    };

#pragma unroll
    for (int s = 0; s < STAGES - 1; s++) load_stage(s, s * BK);

    for (int kt = 0; kt < KT; kt++) {
        asm volatile("cp.async.wait_group %0;" :: "n"(STAGES - 2) : "memory");
        __syncthreads();

        if (kt + STAGES - 1 < KT)
            load_stage((kt + STAGES - 1) % STAGES, (kt + STAGES - 1) * BK);
        else
            asm volatile("cp.async.commit_group;" ::: "memory");

        unsigned stA = sbase + (unsigned)((kt % STAGES) * STAGE_H) * 2u;
        unsigned stB = stA + (unsigned)B_OFF_H * 2u;

#pragma unroll
        for (int kk = 0; kk < 2; kk++) {
            unsigned a[2][4];
#pragma unroll
            for (int mt = 0; mt < 2; mt++) {
                int row = mbase + mt * 16 + ((q & 1) << 3) + rr;
                int kh  = kk * 16 + (q >> 1) * 8;
                ldmatrix_x4(a[mt][0], a[mt][1], a[mt][2], a[mt][3],
                            stA + (unsigned)(row * ROWSTR_H + kh) * 2u);
            }
            unsigned b[8][2];
#pragma unroll
            for (int nt2 = 0; nt2 < 4; nt2++) {
                int row = nbase + nt2 * 16 + ((q >> 1) << 3) + rr;
                int kh  = kk * 16 + (q & 1) * 8;
                ldmatrix_x4(b[nt2 * 2][0], b[nt2 * 2][1], b[nt2 * 2 + 1][0], b[nt2 * 2 + 1][1],
                            stB + (unsigned)(row * ROWSTR_H + kh) * 2u);
            }
#pragma unroll
            for (int mt = 0; mt < 2; mt++)
#pragma unroll
                for (int nt = 0; nt < 8; nt++) {
                    unsigned c0, c1;
                    mma_f16acc(c0, c1, a[mt], b[nt]);
                    float2 f0 = __half22float2(*(__half2*)&c0);
                    float2 f1 = __half22float2(*(__half2*)&c1);
                    acc[mt][nt][0] += f0.x;
                    acc[mt][nt][1] += f0.y;
                    acc[mt][nt][2] += f1.x;
                    acc[mt][nt][3] += f1.y;
                }
        }
    }

    // ---- epilogue: fp32 acc -> fp16 U (natural layout, coalesced) ----
#pragma unroll
    for (int mt = 0; mt < 2; mt++) {
#pragma unroll
        for (int nt = 0; nt < 8; nt++) {
            int row = m0 + mbase + mt * 16 + g;
            int col = n0 + nbase + nt * 8 + 2 * t4;
            __half2 o0 = __floats2half2_rn(acc[mt][nt][0], acc[mt][nt][1]);
            __half2 o1 = __floats2half2_rn(acc[mt][nt][2], acc[mt][nt][3]);
            *(unsigned*)&g_Uh[(size_t)row * N_DIM + col] = *(unsigned*)&o0;
            *(unsigned*)&g_Uh[(size_t)(row + 8) * N_DIM + col] = *(unsigned*)&o1;
        }
    }
}

// ---------------------------------------------------------------------------
// Kernel 3: SRU scan. 16-deep double-buffered prefetch, one chain/thread,
// ex2/rcp approx sigmoid (no div.rn on the serial chain).
// ---------------------------------------------------------------------------
#define PF 16

__global__ void __launch_bounds__(64) sru_scan(const float* __restrict__ X,
                                               const float* __restrict__ C0,
                                               const float* __restrict__ Wc,
                                               const float* __restrict__ Bias,
                                               float* __restrict__ Out,
                                               int write_c) {
    int ch = blockIdx.x * 64 + threadIdx.x;  // 0..16383
    int d = ch & (D_DIM - 1);

    float fw = Wc[d], rw = Wc[D_DIM + d];
    float fb = Bias[d], rb = Bias[D_DIM + d];
    float c = C0[ch];

    // fold -log2e into gate weights/biases (off the serial chain)
    float fwl = -fw * LOG2E, rwl = -rw * LOG2E;
    float fbl = -fb * LOG2E, rbl = -rb * LOG2E;

    const float SC = 1.7320508075688772f;  // sqrt(1 + 2*e^0)
    const __half* up = g_Uh + (size_t)(ch >> 10) * N_DIM + 3 * d;
    const float* xp = X + ch;
    float* hp = Out + ch;

    const int US = B_DIM * N_DIM;   // u stride per step (halves)
    const int XS = B_DIM * D_DIM;   // x stride per step (floats)

    float bu0[2][PF], bu1[2][PF], bu2[2][PF], bx[2][PF];

#pragma unroll
    for (int j = 0; j < PF; j++) {
        const __half* u = up + (size_t)j * US;
        bu0[0][j] = __half2float(u[0]);
        bu1[0][j] = __half2float(u[1]);
        bu2[0][j] = __half2float(u[2]);
        bx[0][j]  = xp[(size_t)j * XS];
    }

#pragma unroll 2
    for (int l = 0; l < L_DIM; l += PF) {
        int p = (l / PF) & 1;
        if (l + PF < L_DIM) {
#pragma unroll
            for (int j = 0; j < PF; j++) {
                const __half* u = up + (size_t)(PF + j) * US;
                bu0[p ^ 1][j] = __half2float(u[0]);
                bu1[p ^ 1][j] = __half2float(u[1]);
                bu2[p ^ 1][j] = __half2float(u[2]);
                bx[p ^ 1][j]  = xp[(size_t)(PF + j) * XS];
            }
        }
#pragma unroll
        for (int j = 0; j < PF; j++) {
            float u0 = bu0[p][j];
            float xv = bx[p][j] * SC;
            float a1 = fmaf(bu1[p][j], -LOG2E, fbl);   // -(u1+fb)*log2e, off chain
            float a2 = fmaf(bu2[p][j], -LOG2E, rbl);
            float f = rcpf(1.0f + ex2f(fmaf(c, fwl, a1)));
            float r = rcpf(1.0f + ex2f(fmaf(c, rwl, a2)));
            c = u0 + (c - u0) * f;
            hp[(size_t)j * XS] = xv + (c - xv) * r;
        }
        up += (size_t)PF * US;
        xp += (size_t)PF * XS;
        hp += (size_t)PF * XS;
    }
    if (write_c) Out[(size_t)L_DIM * B_DIM * D_DIM + ch] = c;
}

// ---------------------------------------------------------------------------
extern "C" void kernel_launch(void* const* d_in, const int* in_sizes, int n_in,
                              void* d_out, int out_size) {
    const float* x    = (const float*)d_in[0];
    const float* c0   = (const float*)d_in[1];
    const float* w    = (const float*)d_in[2];
    const float* wc   = (const float*)d_in[3];
    const float* bias = (const float*)d_in[4];
    float* out = (float*)d_out;

    int write_c = (out_size >= L_DIM * B_DIM * D_DIM + B_DIM * D_DIM) ? 1 : 0;

    static int smem_set = 0;
    if (!smem_set) {
        cudaFuncSetAttribute(gemm_f16, cudaFuncAttributeMaxDynamicSharedMemorySize,
                             GEMM_SMEM_BYTES);
        smem_set = 1;
    }

    convert_x<<<(M_DIM * (K_DIM / 8)) / 256, 256>>>(x);
    transpose_w<<<dim3(N_DIM / 32, K_DIM / 32), dim3(32, 8)>>>(w);
    gemm_f16<<<dim3(N_DIM / BN, M_DIM / BM), 256, GEMM_SMEM_BYTES>>>();
    sru_scan<<<(B_DIM * D_DIM) / 64, 64>>>(x, c0, wc, bias, out, write_c);
}